// round 16
// baseline (speedup 1.0000x reference)
#include <cuda_runtime.h>
#include <cstdint>

#define NN   10000
#define EE   320000
#define FIN  512
#define NHID 32
#define LAT  16
#define PAD  128
#define TT   79      // ceil(10000/128) tiles per dim
#define NTRI 3160    // TT*(TT+1)/2

#define NB_GEMM1 157                  // ceil(10000/64) gemm1 blocks (listed first)
#define NB_BUILD 1250                 // 1250*256 = 320000 edges exactly

#define DEC_SMEM (64 * 1024)          // dynamic smem: union(in-tiles 16KB, ts 64KB)

typedef unsigned long long u64;

// ---------------- device scratch (no allocations allowed) ----------------
// g_cnt invariant: zero at module load; k_spmm2 restores it to zero after
// its reads, so every kernel_launch call (and graph replay) sees zeros.
// g_adj has +16 slack entries for the masked chunk-16 over-reads.
__device__ int   g_cnt[NN];
__device__ int2  g_adj[NN * PAD + 16];
__device__ float g_h0 [NN * NHID];
__device__ float g_z0 [NN * LAT];

// ---------------- f32x2 packed helpers (sm_103a FFMA2 path) --------------
__device__ __forceinline__ u64 fma2(u64 a, u64 b, u64 c) {
    u64 d;
    asm("fma.rn.f32x2 %0, %1, %2, %3;" : "=l"(d) : "l"(a), "l"(b), "l"(c));
    return d;
}
__device__ __forceinline__ u64 pack2(float x) {
    u64 d; asm("mov.b64 %0, {%1, %1};" : "=l"(d) : "f"(x)); return d;
}
__device__ __forceinline__ float lo2(u64 v) {
    float f; asm("{ .reg .f32 h; mov.b64 {%0, h}, %1; }" : "=f"(f) : "l"(v)); return f;
}
__device__ __forceinline__ float hi2(u64 v) {
    float f; asm("{ .reg .f32 l; mov.b64 {l, %0}, %1; }" : "=f"(f) : "l"(v)); return f;
}
__device__ __forceinline__ float sigmoid_fast(float x) {
    float t;
    asm("tanh.approx.f32 %0, %1;" : "=f"(t) : "f"(0.5f * x));
    return fmaf(0.5f, t, 0.5f);
}
__device__ __forceinline__ u64 sig2(u64 x) {
    float lo = sigmoid_fast(lo2(x));
    float hi = sigmoid_fast(hi2(x));
    u64 r; asm("mov.b64 %0, {%1, %2};" : "=l"(r) : "f"(lo), "f"(hi));
    return r;
}

// ------- Fused (no barrier, independent): GEMM1 (blocks 0..156) ----------
// ------- concurrent with edge build (blocks 157..1406) -------------------
// GEMM1: h0[N,32] = x[N,512] @ W1[512,32], FFMA2, k-chunk 32 (32 barriers).
__global__ void __launch_bounds__(256) k_build_gemm1(
        const int*   __restrict__ ei, const float* __restrict__ ew,
        const float* __restrict__ x,  const float* __restrict__ W1) {
    __shared__ float xs[64][36];    // 64 rows x 32 k, pad 36 (conflict-free)
    __shared__ float w1s[32][32];

    int t = threadIdx.x;

    if (blockIdx.x >= NB_GEMM1) {
        // ---- edge build ----
        int e = (blockIdx.x - NB_GEMM1) * 256 + t;   // exact cover of EE
        int   s = ei[e];
        int   d = ei[EE + e];
        float w = ew[e];
        int p = atomicAdd(&g_cnt[d], 1);
        if (p < PAD)
            g_adj[d * PAD + p] = make_int2(s, __float_as_int(w));
        return;
    }

    // ---- GEMM1 tile: 64 rows ----
    int row0 = blockIdx.x * 64;
    int cg   = (t & 7) << 2;
    int rs   = (t >> 3) << 1;

    u64 a00 = 0ull, a01 = 0ull, a10 = 0ull, a11 = 0ull;

    for (int kk = 0; kk < FIN; kk += 32) {
        #pragma unroll
        for (int rep = 0; rep < 2; rep++) {
            int idx = t + rep * 256;
            int r   = idx >> 3;
            int kq  = (idx & 7) << 2;
            int gr  = row0 + r;
            float4 v = make_float4(0.f, 0.f, 0.f, 0.f);
            if (gr < NN) v = *(const float4*)(x + (size_t)gr * FIN + kk + kq);
            *(float4*)&xs[r][kq] = v;
        }
        {
            int k = t >> 3, c = (t & 7) << 2;
            *(float4*)&w1s[k][c] = *(const float4*)(W1 + (size_t)(kk + k) * NHID + c);
        }
        __syncthreads();

        #pragma unroll
        for (int k = 0; k < 32; k++) {
            ulonglong2 bb = *(const ulonglong2*)&w1s[k][cg];
            u64 a0 = pack2(xs[rs][k]);
            u64 a1 = pack2(xs[rs + 1][k]);
            a00 = fma2(a0, bb.x, a00); a01 = fma2(a0, bb.y, a01);
            a10 = fma2(a1, bb.x, a10); a11 = fma2(a1, bb.y, a11);
        }
        __syncthreads();
    }

    int gr0 = row0 + rs;
    if (gr0 < NN)
        *(float4*)&g_h0[(size_t)gr0 * NHID + cg] =
            make_float4(lo2(a00), hi2(a00), lo2(a01), hi2(a01));
    if (gr0 + 1 < NN)
        *(float4*)&g_h0[(size_t)(gr0 + 1) * NHID + cg] =
            make_float4(lo2(a10), hi2(a10), lo2(a11), hi2(a11));
}

// ------- Fused SpMM1 + GEMM2: z0[d,:] = (sum_e w_e*h0[src_e,:]) @ W2 -----
// Warp per node; masked chunk-16 gathers, no serial remainder tail.
__global__ void __launch_bounds__(256) k_spmm1_gemm2(const float* __restrict__ W2) {
    __shared__ float w2s[NHID * LAT];
    {
        int t = threadIdx.x;
        for (int i = t; i < NHID * LAT; i += 256) w2s[i] = W2[i];
    }
    __syncthreads();

    int gid  = blockIdx.x * blockDim.x + threadIdx.x;
    int d    = gid >> 5;
    int lane = gid & 31;
    if (d >= NN) return;
    int cnt = g_cnt[d];
    if (cnt > PAD) cnt = PAD;
    const int2* ap = &g_adj[d * PAD];
    float acc = 0.f;
    for (int j = 0; j < cnt; j += 16) {
        int4 p0 = *(const int4*)(ap + j);
        int4 p1 = *(const int4*)(ap + j + 2);
        int4 p2 = *(const int4*)(ap + j + 4);
        int4 p3 = *(const int4*)(ap + j + 6);
        int4 p4 = *(const int4*)(ap + j + 8);
        int4 p5 = *(const int4*)(ap + j + 10);
        int4 p6 = *(const int4*)(ap + j + 12);
        int4 p7 = *(const int4*)(ap + j + 14);
        int rem = cnt - j;   // >= 1
        float w0  = (0  < rem) ? __int_as_float(p0.y) : 0.f;
        float w1  = (1  < rem) ? __int_as_float(p0.w) : 0.f;
        float w2  = (2  < rem) ? __int_as_float(p1.y) : 0.f;
        float w3  = (3  < rem) ? __int_as_float(p1.w) : 0.f;
        float w4  = (4  < rem) ? __int_as_float(p2.y) : 0.f;
        float w5  = (5  < rem) ? __int_as_float(p2.w) : 0.f;
        float w6  = (6  < rem) ? __int_as_float(p3.y) : 0.f;
        float w7  = (7  < rem) ? __int_as_float(p3.w) : 0.f;
        float w8  = (8  < rem) ? __int_as_float(p4.y) : 0.f;
        float w9  = (9  < rem) ? __int_as_float(p4.w) : 0.f;
        float w10 = (10 < rem) ? __int_as_float(p5.y) : 0.f;
        float w11 = (11 < rem) ? __int_as_float(p5.w) : 0.f;
        float w12 = (12 < rem) ? __int_as_float(p6.y) : 0.f;
        float w13 = (13 < rem) ? __int_as_float(p6.w) : 0.f;
        float w14 = (14 < rem) ? __int_as_float(p7.y) : 0.f;
        float w15 = (15 < rem) ? __int_as_float(p7.w) : 0.f;
        float v0  = g_h0[((size_t)p0.x << 5) + lane];
        float v1  = g_h0[((size_t)p0.z << 5) + lane];
        float v2  = g_h0[((size_t)p1.x << 5) + lane];
        float v3  = g_h0[((size_t)p1.z << 5) + lane];
        float v4  = g_h0[((size_t)p2.x << 5) + lane];
        float v5  = g_h0[((size_t)p2.z << 5) + lane];
        float v6  = g_h0[((size_t)p3.x << 5) + lane];
        float v7  = g_h0[((size_t)p3.z << 5) + lane];
        float v8  = g_h0[((size_t)p4.x << 5) + lane];
        float v9  = g_h0[((size_t)p4.z << 5) + lane];
        float v10 = g_h0[((size_t)p5.x << 5) + lane];
        float v11 = g_h0[((size_t)p5.z << 5) + lane];
        float v12 = g_h0[((size_t)p6.x << 5) + lane];
        float v13 = g_h0[((size_t)p6.z << 5) + lane];
        float v14 = g_h0[((size_t)p7.x << 5) + lane];
        float v15 = g_h0[((size_t)p7.z << 5) + lane];
        acc = fmaf(w0,  v0,  acc); acc = fmaf(w1,  v1,  acc);
        acc = fmaf(w2,  v2,  acc); acc = fmaf(w3,  v3,  acc);
        acc = fmaf(w4,  v4,  acc); acc = fmaf(w5,  v5,  acc);
        acc = fmaf(w6,  v6,  acc); acc = fmaf(w7,  v7,  acc);
        acc = fmaf(w8,  v8,  acc); acc = fmaf(w9,  v9,  acc);
        acc = fmaf(w10, v10, acc); acc = fmaf(w11, v11, acc);
        acc = fmaf(w12, v12, acc); acc = fmaf(w13, v13, acc);
        acc = fmaf(w14, v14, acc); acc = fmaf(w15, v15, acc);
    }

    // h[d,:] distributed across lanes; z0[d,c] via shfl broadcast
    int c = lane & 15;
    float zc = 0.f;
    #pragma unroll
    for (int k = 0; k < NHID; k++) {
        float hk = __shfl_sync(0xffffffffu, acc, k);
        zc = fmaf(hk, w2s[k * LAT + c], zc);
    }
    if (lane < LAT)
        g_z0[((size_t)d << 4) + c] = zc;
}

// ------- SpMM2 (+ restore g_cnt=0): 32 threads/node, 2 edge halves -------
// Warp = one node; lane = h*16 + c. Half h processes chunk-16 groups
// j = 16h, 16h+32, ... of the node's edge list; combine via shfl_xor(16).
// Grid: 1250 blocks x 256 = 10000 warps exactly (no divergent exits).
__global__ void __launch_bounds__(256) k_spmm2(float* __restrict__ zout) {
    int gid  = blockIdx.x * blockDim.x + threadIdx.x;
    int d    = gid >> 5;
    int lane = gid & 31;
    int c    = lane & 15;
    int h    = lane >> 4;

    int cnt = g_cnt[d];
    if (cnt > PAD) cnt = PAD;
    __syncwarp();                     // all reads of g_cnt in this warp done
    if (lane == 0) g_cnt[d] = 0;      // restore invariant for next launch

    const int2* ap = &g_adj[d * PAD];
    float acc = 0.f;
    for (int j = h * 16; j < cnt; j += 32) {
        int4 p0 = *(const int4*)(ap + j);
        int4 p1 = *(const int4*)(ap + j + 2);
        int4 p2 = *(const int4*)(ap + j + 4);
        int4 p3 = *(const int4*)(ap + j + 6);
        int4 p4 = *(const int4*)(ap + j + 8);
        int4 p5 = *(const int4*)(ap + j + 10);
        int4 p6 = *(const int4*)(ap + j + 12);
        int4 p7 = *(const int4*)(ap + j + 14);
        int rem = cnt - j;            // >= 1
        float w0  = (0  < rem) ? __int_as_float(p0.y) : 0.f;
        float w1  = (1  < rem) ? __int_as_float(p0.w) : 0.f;
        float w2  = (2  < rem) ? __int_as_float(p1.y) : 0.f;
        float w3  = (3  < rem) ? __int_as_float(p1.w) : 0.f;
        float w4  = (4  < rem) ? __int_as_float(p2.y) : 0.f;
        float w5  = (5  < rem) ? __int_as_float(p2.w) : 0.f;
        float w6  = (6  < rem) ? __int_as_float(p3.y) : 0.f;
        float w7  = (7  < rem) ? __int_as_float(p3.w) : 0.f;
        float w8  = (8  < rem) ? __int_as_float(p4.y) : 0.f;
        float w9  = (9  < rem) ? __int_as_float(p4.w) : 0.f;
        float w10 = (10 < rem) ? __int_as_float(p5.y) : 0.f;
        float w11 = (11 < rem) ? __int_as_float(p5.w) : 0.f;
        float w12 = (12 < rem) ? __int_as_float(p6.y) : 0.f;
        float w13 = (13 < rem) ? __int_as_float(p6.w) : 0.f;
        float w14 = (14 < rem) ? __int_as_float(p7.y) : 0.f;
        float w15 = (15 < rem) ? __int_as_float(p7.w) : 0.f;
        float v0  = g_z0[((size_t)p0.x << 4) + c];
        float v1  = g_z0[((size_t)p0.z << 4) + c];
        float v2  = g_z0[((size_t)p1.x << 4) + c];
        float v3  = g_z0[((size_t)p1.z << 4) + c];
        float v4  = g_z0[((size_t)p2.x << 4) + c];
        float v5  = g_z0[((size_t)p2.z << 4) + c];
        float v6  = g_z0[((size_t)p3.x << 4) + c];
        float v7  = g_z0[((size_t)p3.z << 4) + c];
        float v8  = g_z0[((size_t)p4.x << 4) + c];
        float v9  = g_z0[((size_t)p4.z << 4) + c];
        float v10 = g_z0[((size_t)p5.x << 4) + c];
        float v11 = g_z0[((size_t)p5.z << 4) + c];
        float v12 = g_z0[((size_t)p6.x << 4) + c];
        float v13 = g_z0[((size_t)p6.z << 4) + c];
        float v14 = g_z0[((size_t)p7.x << 4) + c];
        float v15 = g_z0[((size_t)p7.z << 4) + c];
        acc = fmaf(w0,  v0,  acc); acc = fmaf(w1,  v1,  acc);
        acc = fmaf(w2,  v2,  acc); acc = fmaf(w3,  v3,  acc);
        acc = fmaf(w4,  v4,  acc); acc = fmaf(w5,  v5,  acc);
        acc = fmaf(w6,  v6,  acc); acc = fmaf(w7,  v7,  acc);
        acc = fmaf(w8,  v8,  acc); acc = fmaf(w9,  v9,  acc);
        acc = fmaf(w10, v10, acc); acc = fmaf(w11, v11, acc);
        acc = fmaf(w12, v12, acc); acc = fmaf(w13, v13, acc);
        acc = fmaf(w14, v14, acc); acc = fmaf(w15, v15, acc);
    }

    acc += __shfl_xor_sync(0xffffffffu, acc, 16);   // combine halves
    if (h == 0)
        zout[((size_t)d << 4) + c] = acc;
}

// ---------------- Decoder: adj = sigmoid(z @ z^T), symmetric -------------
// R15 (proven): dynamic 64KB smem, single-pass mirror, FFMA2 mainloop.
struct DecIn { float4 a[16][2][16]; float4 b[16][2][16]; };

__global__ void __launch_bounds__(256, 2) k_dec(const float* __restrict__ z,
                                                float* __restrict__ out) {
    extern __shared__ char dsm[];
    DecIn* in  = (DecIn*)dsm;
    float* tsf = (float*)dsm;        // reused after the post-mainloop barrier

    int b  = blockIdx.x;
    int bi = (int)((159.0f - sqrtf(25281.0f - 8.0f * (float)b)) * 0.5f);
    while (((bi + 1) * TT - ((bi + 1) * bi) / 2) <= b) bi++;
    while ((bi * TT - (bi * (bi - 1)) / 2) > b) bi--;
    int bj = bi + (b - (bi * TT - (bi * (bi - 1)) / 2));

    int t  = threadIdx.x;
    int i0 = bi * 128;
    int j0 = bj * 128;

    #pragma unroll
    for (int rep = 0; rep < 2; rep++) {
        int idx  = t + rep * 256;
        int r    = idx >> 2;
        int kq4  = idx & 3;
        int part = (r >> 2) & 1;
        int g    = r >> 3;
        int e    = r & 3;

        int gi = i0 + r;
        float4 v = make_float4(0.f, 0.f, 0.f, 0.f);
        if (gi < NN) v = *(const float4*)(z + (size_t)gi * LAT + kq4 * 4);
        ((float*)&in->a[kq4 * 4 + 0][part][g])[e] = v.x;
        ((float*)&in->a[kq4 * 4 + 1][part][g])[e] = v.y;
        ((float*)&in->a[kq4 * 4 + 2][part][g])[e] = v.z;
        ((float*)&in->a[kq4 * 4 + 3][part][g])[e] = v.w;

        int gj = j0 + r;
        float4 u = make_float4(0.f, 0.f, 0.f, 0.f);
        if (gj < NN) u = *(const float4*)(z + (size_t)gj * LAT + kq4 * 4);
        ((float*)&in->b[kq4 * 4 + 0][part][g])[e] = u.x;
        ((float*)&in->b[kq4 * 4 + 1][part][g])[e] = u.y;
        ((float*)&in->b[kq4 * 4 + 2][part][g])[e] = u.z;
        ((float*)&in->b[kq4 * 4 + 3][part][g])[e] = u.w;
    }
    __syncthreads();

    int tx = t & 15, ty = t >> 4;
    int ib = ty << 3, jb = tx << 3;

    u64 acc2[8][4];
    #pragma unroll
    for (int r = 0; r < 8; r++)
        #pragma unroll
        for (int q = 0; q < 4; q++) acc2[r][q] = 0ull;

    #pragma unroll
    for (int k = 0; k < 16; k++) {
        float4 Alo = in->a[k][0][ty];
        float4 Ahi = in->a[k][1][ty];
        ulonglong2 B0 = *(const ulonglong2*)&in->b[k][0][tx];
        ulonglong2 B1 = *(const ulonglong2*)&in->b[k][1][tx];
        u64 ar;
        ar = pack2(Alo.x);
        acc2[0][0] = fma2(ar, B0.x, acc2[0][0]); acc2[0][1] = fma2(ar, B0.y, acc2[0][1]);
        acc2[0][2] = fma2(ar, B1.x, acc2[0][2]); acc2[0][3] = fma2(ar, B1.y, acc2[0][3]);
        ar = pack2(Alo.y);
        acc2[1][0] = fma2(ar, B0.x, acc2[1][0]); acc2[1][1] = fma2(ar, B0.y, acc2[1][1]);
        acc2[1][2] = fma2(ar, B1.x, acc2[1][2]); acc2[1][3] = fma2(ar, B1.y, acc2[1][3]);
        ar = pack2(Alo.z);
        acc2[2][0] = fma2(ar, B0.x, acc2[2][0]); acc2[2][1] = fma2(ar, B0.y, acc2[2][1]);
        acc2[2][2] = fma2(ar, B1.x, acc2[2][2]); acc2[2][3] = fma2(ar, B1.y, acc2[2][3]);
        ar = pack2(Alo.w);
        acc2[3][0] = fma2(ar, B0.x, acc2[3][0]); acc2[3][1] = fma2(ar, B0.y, acc2[3][1]);
        acc2[3][2] = fma2(ar, B1.x, acc2[3][2]); acc2[3][3] = fma2(ar, B1.y, acc2[3][3]);
        ar = pack2(Ahi.x);
        acc2[4][0] = fma2(ar, B0.x, acc2[4][0]); acc2[4][1] = fma2(ar, B0.y, acc2[4][1]);
        acc2[4][2] = fma2(ar, B1.x, acc2[4][2]); acc2[4][3] = fma2(ar, B1.y, acc2[4][3]);
        ar = pack2(Ahi.y);
        acc2[5][0] = fma2(ar, B0.x, acc2[5][0]); acc2[5][1] = fma2(ar, B0.y, acc2[5][1]);
        acc2[5][2] = fma2(ar, B1.x, acc2[5][2]); acc2[5][3] = fma2(ar, B1.y, acc2[5][3]);
        ar = pack2(Ahi.z);
        acc2[6][0] = fma2(ar, B0.x, acc2[6][0]); acc2[6][1] = fma2(ar, B0.y, acc2[6][1]);
        acc2[6][2] = fma2(ar, B1.x, acc2[6][2]); acc2[6][3] = fma2(ar, B1.y, acc2[6][3]);
        ar = pack2(Ahi.w);
        acc2[7][0] = fma2(ar, B0.x, acc2[7][0]); acc2[7][1] = fma2(ar, B0.y, acc2[7][1]);
        acc2[7][2] = fma2(ar, B1.x, acc2[7][2]); acc2[7][3] = fma2(ar, B1.y, acc2[7][3]);
    }

    // ---- sigmoid + normal write interleaved per row ----
    int gjw = j0 + jb;
    #pragma unroll
    for (int r = 0; r < 8; r++) {
        acc2[r][0] = sig2(acc2[r][0]);
        acc2[r][1] = sig2(acc2[r][1]);
        acc2[r][2] = sig2(acc2[r][2]);
        acc2[r][3] = sig2(acc2[r][3]);
        int gi = i0 + ib + r;
        if (gi < NN && gjw < NN) {
            float4 o0 = make_float4(lo2(acc2[r][0]), hi2(acc2[r][0]),
                                    lo2(acc2[r][1]), hi2(acc2[r][1]));
            float4 o1 = make_float4(lo2(acc2[r][2]), hi2(acc2[r][2]),
                                    lo2(acc2[r][3]), hi2(acc2[r][3]));
            float* p = out + (size_t)gi * NN + gjw;
            __stcs((float4*)p, o0);
            __stcs((float4*)(p + 4), o1);
        }
    }

    if (bj == bi) return;   // diagonal tile: no mirror (all threads uniform)

    // ---- mirror write: single-pass full 128x128 transpose ----
    __syncthreads();        // all threads done reading in-tiles
    {
        int key    = tx & 7;         // = ((jb+c)>>3)&7 for all c in 0..7
        int c4base = ty << 1;        // = ib>>2
        #pragma unroll
        for (int c = 0; c < 8; c++) {
            int row = jb + c;        // staged j-local row 0..127
            int q   = c >> 1;
            float4 v0, v1;
            if (c & 1) {
                v0 = make_float4(hi2(acc2[0][q]), hi2(acc2[1][q]),
                                 hi2(acc2[2][q]), hi2(acc2[3][q]));
                v1 = make_float4(hi2(acc2[4][q]), hi2(acc2[5][q]),
                                 hi2(acc2[6][q]), hi2(acc2[7][q]));
            } else {
                v0 = make_float4(lo2(acc2[0][q]), lo2(acc2[1][q]),
                                 lo2(acc2[2][q]), lo2(acc2[3][q]));
                v1 = make_float4(lo2(acc2[4][q]), lo2(acc2[5][q]),
                                 lo2(acc2[6][q]), lo2(acc2[7][q]));
            }
            *(float4*)(tsf + row * 128 + (((c4base)     ^ key) << 2)) = v0;
            *(float4*)(tsf + row * 128 + (((c4base + 1) ^ key) << 2)) = v1;
        }
    }
    __syncthreads();
    {
        int warp = t >> 5, lane = t & 31;
        #pragma unroll
        for (int s = 0; s < 16; s++) {
            int row = (warp << 4) | s;           // j-local 0..127
            int key = (row >> 3) & 7;
            float4 val = *(const float4*)(tsf + row * 128 + ((lane ^ key) << 2));
            int gj = j0 + row;
            int gi = i0 + (lane << 2);
            if (gj < NN && gi < NN)
                __stcs((float4*)(out + (size_t)gj * NN + gi), val);
        }
    }
}

// ---------------- launch --------------------------------------------------
extern "C" void kernel_launch(void* const* d_in, const int* in_sizes, int n_in,
                              void* d_out, int out_size) {
    const float* x  = (const float*)d_in[0];
    const float* W1 = (const float*)d_in[1];
    const float* W2 = (const float*)d_in[2];
    const int*   ei = (const int*)  d_in[3];
    const float* ew = (const float*)d_in[4];

    float* out  = (float*)d_out;
    float* zout = out + (size_t)NN * NN;   // output layout: [adj (1e8) | z]

    cudaFuncSetAttribute(k_dec, cudaFuncAttributeMaxDynamicSharedMemorySize,
                         DEC_SMEM);

    k_build_gemm1<<<NB_GEMM1 + NB_BUILD, 256>>>(ei, ew, x, W1);
    k_spmm1_gemm2<<<(NN * 32 + 255) / 256, 256>>>(W2);
    k_spmm2      <<<(NN * 32) / 256, 256>>>(zout);
    k_dec        <<<NTRI, 256, DEC_SMEM>>>(zout, out);
}

// round 17
// speedup vs baseline: 1.1008x; 1.1008x over previous
#include <cuda_runtime.h>
#include <cstdint>

#define NN   10000
#define EE   320000
#define FIN  512
#define NHID 32
#define LAT  16
#define PAD  128
#define TT   79      // ceil(10000/128) tiles per dim
#define NTRI 3160    // TT*(TT+1)/2

#define NB_GEMM1 157                  // ceil(10000/64) gemm1 blocks (listed first)
#define NB_BUILD 1250                 // 1250*256 = 320000 edges exactly

#define DEC_SMEM (64 * 1024)          // dynamic smem: union(in-tiles 16KB, ts 64KB)

typedef unsigned long long u64;

// ---------------- device scratch (no allocations allowed) ----------------
// g_cnt invariant: zero at module load; k_spmm2 restores it to zero after
// its reads, so every kernel_launch call (and graph replay) sees zeros.
// g_adj has +16 slack entries for the masked chunk-16 over-reads.
__device__ int   g_cnt[NN];
__device__ int2  g_adj[NN * PAD + 16];
__device__ float g_h0 [NN * NHID];
__device__ float g_z0 [NN * LAT];

// ---------------- f32x2 packed helpers (sm_103a FFMA2 path) --------------
__device__ __forceinline__ u64 fma2(u64 a, u64 b, u64 c) {
    u64 d;
    asm("fma.rn.f32x2 %0, %1, %2, %3;" : "=l"(d) : "l"(a), "l"(b), "l"(c));
    return d;
}
__device__ __forceinline__ u64 pack2(float x) {
    u64 d; asm("mov.b64 %0, {%1, %1};" : "=l"(d) : "f"(x)); return d;
}
__device__ __forceinline__ float lo2(u64 v) {
    float f; asm("{ .reg .f32 h; mov.b64 {%0, h}, %1; }" : "=f"(f) : "l"(v)); return f;
}
__device__ __forceinline__ float hi2(u64 v) {
    float f; asm("{ .reg .f32 l; mov.b64 {l, %0}, %1; }" : "=f"(f) : "l"(v)); return f;
}
__device__ __forceinline__ float sigmoid_fast(float x) {
    float t;
    asm("tanh.approx.f32 %0, %1;" : "=f"(t) : "f"(0.5f * x));
    return fmaf(0.5f, t, 0.5f);
}
__device__ __forceinline__ u64 sig2(u64 x) {
    float lo = sigmoid_fast(lo2(x));
    float hi = sigmoid_fast(hi2(x));
    u64 r; asm("mov.b64 %0, {%1, %2};" : "=l"(r) : "f"(lo), "f"(hi));
    return r;
}

// ------- Fused (no barrier, independent): GEMM1 (blocks 0..156) ----------
// ------- concurrent with edge build (blocks 157..1406) -------------------
// GEMM1: h0[N,32] = x[N,512] @ W1[512,32], FFMA2, k-chunk 32 (32 barriers).
__global__ void __launch_bounds__(256) k_build_gemm1(
        const int*   __restrict__ ei, const float* __restrict__ ew,
        const float* __restrict__ x,  const float* __restrict__ W1) {
    __shared__ float xs[64][36];    // 64 rows x 32 k, pad 36 (conflict-free)
    __shared__ float w1s[32][32];

    int t = threadIdx.x;

    if (blockIdx.x >= NB_GEMM1) {
        // ---- edge build ----
        int e = (blockIdx.x - NB_GEMM1) * 256 + t;   // exact cover of EE
        int   s = ei[e];
        int   d = ei[EE + e];
        float w = ew[e];
        int p = atomicAdd(&g_cnt[d], 1);
        if (p < PAD)
            g_adj[d * PAD + p] = make_int2(s, __float_as_int(w));
        return;
    }

    // ---- GEMM1 tile: 64 rows ----
    int row0 = blockIdx.x * 64;
    int cg   = (t & 7) << 2;
    int rs   = (t >> 3) << 1;

    u64 a00 = 0ull, a01 = 0ull, a10 = 0ull, a11 = 0ull;

    for (int kk = 0; kk < FIN; kk += 32) {
        #pragma unroll
        for (int rep = 0; rep < 2; rep++) {
            int idx = t + rep * 256;
            int r   = idx >> 3;
            int kq  = (idx & 7) << 2;
            int gr  = row0 + r;
            float4 v = make_float4(0.f, 0.f, 0.f, 0.f);
            if (gr < NN) v = *(const float4*)(x + (size_t)gr * FIN + kk + kq);
            *(float4*)&xs[r][kq] = v;
        }
        {
            int k = t >> 3, c = (t & 7) << 2;
            *(float4*)&w1s[k][c] = *(const float4*)(W1 + (size_t)(kk + k) * NHID + c);
        }
        __syncthreads();

        #pragma unroll
        for (int k = 0; k < 32; k++) {
            ulonglong2 bb = *(const ulonglong2*)&w1s[k][cg];
            u64 a0 = pack2(xs[rs][k]);
            u64 a1 = pack2(xs[rs + 1][k]);
            a00 = fma2(a0, bb.x, a00); a01 = fma2(a0, bb.y, a01);
            a10 = fma2(a1, bb.x, a10); a11 = fma2(a1, bb.y, a11);
        }
        __syncthreads();
    }

    int gr0 = row0 + rs;
    if (gr0 < NN)
        *(float4*)&g_h0[(size_t)gr0 * NHID + cg] =
            make_float4(lo2(a00), hi2(a00), lo2(a01), hi2(a01));
    if (gr0 + 1 < NN)
        *(float4*)&g_h0[(size_t)(gr0 + 1) * NHID + cg] =
            make_float4(lo2(a10), hi2(a10), lo2(a11), hi2(a11));
}

// ------- Fused SpMM1 + GEMM2: z0[d,:] = (sum_e w_e*h0[src_e,:]) @ W2 -----
// Warp per node; masked chunk-16 gathers, no serial remainder tail.
__global__ void __launch_bounds__(256) k_spmm1_gemm2(const float* __restrict__ W2) {
    __shared__ float w2s[NHID * LAT];
    {
        int t = threadIdx.x;
        for (int i = t; i < NHID * LAT; i += 256) w2s[i] = W2[i];
    }
    __syncthreads();

    int gid  = blockIdx.x * blockDim.x + threadIdx.x;
    int d    = gid >> 5;
    int lane = gid & 31;
    if (d >= NN) return;
    int cnt = g_cnt[d];
    if (cnt > PAD) cnt = PAD;
    const int2* ap = &g_adj[d * PAD];
    float acc = 0.f;
    for (int j = 0; j < cnt; j += 16) {
        int4 p0 = *(const int4*)(ap + j);
        int4 p1 = *(const int4*)(ap + j + 2);
        int4 p2 = *(const int4*)(ap + j + 4);
        int4 p3 = *(const int4*)(ap + j + 6);
        int4 p4 = *(const int4*)(ap + j + 8);
        int4 p5 = *(const int4*)(ap + j + 10);
        int4 p6 = *(const int4*)(ap + j + 12);
        int4 p7 = *(const int4*)(ap + j + 14);
        int rem = cnt - j;   // >= 1
        float w0  = (0  < rem) ? __int_as_float(p0.y) : 0.f;
        float w1  = (1  < rem) ? __int_as_float(p0.w) : 0.f;
        float w2  = (2  < rem) ? __int_as_float(p1.y) : 0.f;
        float w3  = (3  < rem) ? __int_as_float(p1.w) : 0.f;
        float w4  = (4  < rem) ? __int_as_float(p2.y) : 0.f;
        float w5  = (5  < rem) ? __int_as_float(p2.w) : 0.f;
        float w6  = (6  < rem) ? __int_as_float(p3.y) : 0.f;
        float w7  = (7  < rem) ? __int_as_float(p3.w) : 0.f;
        float w8  = (8  < rem) ? __int_as_float(p4.y) : 0.f;
        float w9  = (9  < rem) ? __int_as_float(p4.w) : 0.f;
        float w10 = (10 < rem) ? __int_as_float(p5.y) : 0.f;
        float w11 = (11 < rem) ? __int_as_float(p5.w) : 0.f;
        float w12 = (12 < rem) ? __int_as_float(p6.y) : 0.f;
        float w13 = (13 < rem) ? __int_as_float(p6.w) : 0.f;
        float w14 = (14 < rem) ? __int_as_float(p7.y) : 0.f;
        float w15 = (15 < rem) ? __int_as_float(p7.w) : 0.f;
        float v0  = g_h0[((size_t)p0.x << 5) + lane];
        float v1  = g_h0[((size_t)p0.z << 5) + lane];
        float v2  = g_h0[((size_t)p1.x << 5) + lane];
        float v3  = g_h0[((size_t)p1.z << 5) + lane];
        float v4  = g_h0[((size_t)p2.x << 5) + lane];
        float v5  = g_h0[((size_t)p2.z << 5) + lane];
        float v6  = g_h0[((size_t)p3.x << 5) + lane];
        float v7  = g_h0[((size_t)p3.z << 5) + lane];
        float v8  = g_h0[((size_t)p4.x << 5) + lane];
        float v9  = g_h0[((size_t)p4.z << 5) + lane];
        float v10 = g_h0[((size_t)p5.x << 5) + lane];
        float v11 = g_h0[((size_t)p5.z << 5) + lane];
        float v12 = g_h0[((size_t)p6.x << 5) + lane];
        float v13 = g_h0[((size_t)p6.z << 5) + lane];
        float v14 = g_h0[((size_t)p7.x << 5) + lane];
        float v15 = g_h0[((size_t)p7.z << 5) + lane];
        acc = fmaf(w0,  v0,  acc); acc = fmaf(w1,  v1,  acc);
        acc = fmaf(w2,  v2,  acc); acc = fmaf(w3,  v3,  acc);
        acc = fmaf(w4,  v4,  acc); acc = fmaf(w5,  v5,  acc);
        acc = fmaf(w6,  v6,  acc); acc = fmaf(w7,  v7,  acc);
        acc = fmaf(w8,  v8,  acc); acc = fmaf(w9,  v9,  acc);
        acc = fmaf(w10, v10, acc); acc = fmaf(w11, v11, acc);
        acc = fmaf(w12, v12, acc); acc = fmaf(w13, v13, acc);
        acc = fmaf(w14, v14, acc); acc = fmaf(w15, v15, acc);
    }

    // h[d,:] distributed across lanes; z0[d,c] via shfl broadcast
    int c = lane & 15;
    float zc = 0.f;
    #pragma unroll
    for (int k = 0; k < NHID; k++) {
        float hk = __shfl_sync(0xffffffffu, acc, k);
        zc = fmaf(hk, w2s[k * LAT + c], zc);
    }
    if (lane < LAT)
        g_z0[((size_t)d << 4) + c] = zc;
}

// ------- SpMM2 (+ restore g_cnt=0 for the next call) ---------------------
// grid covers exactly NN*16 threads (625 blocks x 256) -> no divergent exit.
__global__ void __launch_bounds__(256) k_spmm2(float* __restrict__ zout) {
    int gid = blockIdx.x * blockDim.x + threadIdx.x;
    int d   = gid >> 4;
    int c   = gid & 15;
    int cnt = g_cnt[d];
    if (cnt > PAD) cnt = PAD;
    __syncwarp();                 // all reads of g_cnt in this warp done
    if (c == 0) g_cnt[d] = 0;     // restore invariant for next launch

    const int2* ap = &g_adj[d * PAD];
    float acc = 0.f;
    for (int j = 0; j < cnt; j += 16) {
        int4 p0 = *(const int4*)(ap + j);
        int4 p1 = *(const int4*)(ap + j + 2);
        int4 p2 = *(const int4*)(ap + j + 4);
        int4 p3 = *(const int4*)(ap + j + 6);
        int4 p4 = *(const int4*)(ap + j + 8);
        int4 p5 = *(const int4*)(ap + j + 10);
        int4 p6 = *(const int4*)(ap + j + 12);
        int4 p7 = *(const int4*)(ap + j + 14);
        int rem = cnt - j;
        float w0  = (0  < rem) ? __int_as_float(p0.y) : 0.f;
        float w1  = (1  < rem) ? __int_as_float(p0.w) : 0.f;
        float w2  = (2  < rem) ? __int_as_float(p1.y) : 0.f;
        float w3  = (3  < rem) ? __int_as_float(p1.w) : 0.f;
        float w4  = (4  < rem) ? __int_as_float(p2.y) : 0.f;
        float w5  = (5  < rem) ? __int_as_float(p2.w) : 0.f;
        float w6  = (6  < rem) ? __int_as_float(p3.y) : 0.f;
        float w7  = (7  < rem) ? __int_as_float(p3.w) : 0.f;
        float w8  = (8  < rem) ? __int_as_float(p4.y) : 0.f;
        float w9  = (9  < rem) ? __int_as_float(p4.w) : 0.f;
        float w10 = (10 < rem) ? __int_as_float(p5.y) : 0.f;
        float w11 = (11 < rem) ? __int_as_float(p5.w) : 0.f;
        float w12 = (12 < rem) ? __int_as_float(p6.y) : 0.f;
        float w13 = (13 < rem) ? __int_as_float(p6.w) : 0.f;
        float w14 = (14 < rem) ? __int_as_float(p7.y) : 0.f;
        float w15 = (15 < rem) ? __int_as_float(p7.w) : 0.f;
        float v0  = g_z0[((size_t)p0.x << 4) + c];
        float v1  = g_z0[((size_t)p0.z << 4) + c];
        float v2  = g_z0[((size_t)p1.x << 4) + c];
        float v3  = g_z0[((size_t)p1.z << 4) + c];
        float v4  = g_z0[((size_t)p2.x << 4) + c];
        float v5  = g_z0[((size_t)p2.z << 4) + c];
        float v6  = g_z0[((size_t)p3.x << 4) + c];
        float v7  = g_z0[((size_t)p3.z << 4) + c];
        float v8  = g_z0[((size_t)p4.x << 4) + c];
        float v9  = g_z0[((size_t)p4.z << 4) + c];
        float v10 = g_z0[((size_t)p5.x << 4) + c];
        float v11 = g_z0[((size_t)p5.z << 4) + c];
        float v12 = g_z0[((size_t)p6.x << 4) + c];
        float v13 = g_z0[((size_t)p6.z << 4) + c];
        float v14 = g_z0[((size_t)p7.x << 4) + c];
        float v15 = g_z0[((size_t)p7.z << 4) + c];
        acc = fmaf(w0,  v0,  acc); acc = fmaf(w1,  v1,  acc);
        acc = fmaf(w2,  v2,  acc); acc = fmaf(w3,  v3,  acc);
        acc = fmaf(w4,  v4,  acc); acc = fmaf(w5,  v5,  acc);
        acc = fmaf(w6,  v6,  acc); acc = fmaf(w7,  v7,  acc);
        acc = fmaf(w8,  v8,  acc); acc = fmaf(w9,  v9,  acc);
        acc = fmaf(w10, v10, acc); acc = fmaf(w11, v11, acc);
        acc = fmaf(w12, v12, acc); acc = fmaf(w13, v13, acc);
        acc = fmaf(w14, v14, acc); acc = fmaf(w15, v15, acc);
    }
    zout[((size_t)d << 4) + c] = acc;
}

// ---------------- Decoder: adj = sigmoid(z @ z^T), symmetric -------------
// R6 mainloop (proven); dynamic 64KB smem: union of the 16KB input tiles
// and a full 128x128 transpose buffer -> SINGLE-pass mirror (2 barriers
// instead of 4, unbroken mirror store stream). XOR key (row>>3)&7 keeps
// all staging STS / LDS phases conflict-free.
struct DecIn { float4 a[16][2][16]; float4 b[16][2][16]; };

__global__ void __launch_bounds__(256, 2) k_dec(const float* __restrict__ z,
                                                float* __restrict__ out) {
    extern __shared__ char dsm[];
    DecIn* in  = (DecIn*)dsm;
    float* tsf = (float*)dsm;        // reused after the post-mainloop barrier

    int b  = blockIdx.x;
    int bi = (int)((159.0f - sqrtf(25281.0f - 8.0f * (float)b)) * 0.5f);
    while (((bi + 1) * TT - ((bi + 1) * bi) / 2) <= b) bi++;
    while ((bi * TT - (bi * (bi - 1)) / 2) > b) bi--;
    int bj = bi + (b - (bi * TT - (bi * (bi - 1)) / 2));

    int t  = threadIdx.x;
    int i0 = bi * 128;
    int j0 = bj * 128;

    #pragma unroll
    for (int rep = 0; rep < 2; rep++) {
        int idx  = t + rep * 256;
        int r    = idx >> 2;
        int kq4  = idx & 3;
        int part = (r >> 2) & 1;
        int g    = r >> 3;
        int e    = r & 3;

        int gi = i0 + r;
        float4 v = make_float4(0.f, 0.f, 0.f, 0.f);
        if (gi < NN) v = *(const float4*)(z + (size_t)gi * LAT + kq4 * 4);
        ((float*)&in->a[kq4 * 4 + 0][part][g])[e] = v.x;
        ((float*)&in->a[kq4 * 4 + 1][part][g])[e] = v.y;
        ((float*)&in->a[kq4 * 4 + 2][part][g])[e] = v.z;
        ((float*)&in->a[kq4 * 4 + 3][part][g])[e] = v.w;

        int gj = j0 + r;
        float4 u = make_float4(0.f, 0.f, 0.f, 0.f);
        if (gj < NN) u = *(const float4*)(z + (size_t)gj * LAT + kq4 * 4);
        ((float*)&in->b[kq4 * 4 + 0][part][g])[e] = u.x;
        ((float*)&in->b[kq4 * 4 + 1][part][g])[e] = u.y;
        ((float*)&in->b[kq4 * 4 + 2][part][g])[e] = u.z;
        ((float*)&in->b[kq4 * 4 + 3][part][g])[e] = u.w;
    }
    __syncthreads();

    int tx = t & 15, ty = t >> 4;
    int ib = ty << 3, jb = tx << 3;

    u64 acc2[8][4];
    #pragma unroll
    for (int r = 0; r < 8; r++)
        #pragma unroll
        for (int q = 0; q < 4; q++) acc2[r][q] = 0ull;

    #pragma unroll
    for (int k = 0; k < 16; k++) {
        float4 Alo = in->a[k][0][ty];
        float4 Ahi = in->a[k][1][ty];
        ulonglong2 B0 = *(const ulonglong2*)&in->b[k][0][tx];
        ulonglong2 B1 = *(const ulonglong2*)&in->b[k][1][tx];
        u64 ar;
        ar = pack2(Alo.x);
        acc2[0][0] = fma2(ar, B0.x, acc2[0][0]); acc2[0][1] = fma2(ar, B0.y, acc2[0][1]);
        acc2[0][2] = fma2(ar, B1.x, acc2[0][2]); acc2[0][3] = fma2(ar, B1.y, acc2[0][3]);
        ar = pack2(Alo.y);
        acc2[1][0] = fma2(ar, B0.x, acc2[1][0]); acc2[1][1] = fma2(ar, B0.y, acc2[1][1]);
        acc2[1][2] = fma2(ar, B1.x, acc2[1][2]); acc2[1][3] = fma2(ar, B1.y, acc2[1][3]);
        ar = pack2(Alo.z);
        acc2[2][0] = fma2(ar, B0.x, acc2[2][0]); acc2[2][1] = fma2(ar, B0.y, acc2[2][1]);
        acc2[2][2] = fma2(ar, B1.x, acc2[2][2]); acc2[2][3] = fma2(ar, B1.y, acc2[2][3]);
        ar = pack2(Alo.w);
        acc2[3][0] = fma2(ar, B0.x, acc2[3][0]); acc2[3][1] = fma2(ar, B0.y, acc2[3][1]);
        acc2[3][2] = fma2(ar, B1.x, acc2[3][2]); acc2[3][3] = fma2(ar, B1.y, acc2[3][3]);
        ar = pack2(Ahi.x);
        acc2[4][0] = fma2(ar, B0.x, acc2[4][0]); acc2[4][1] = fma2(ar, B0.y, acc2[4][1]);
        acc2[4][2] = fma2(ar, B1.x, acc2[4][2]); acc2[4][3] = fma2(ar, B1.y, acc2[4][3]);
        ar = pack2(Ahi.y);
        acc2[5][0] = fma2(ar, B0.x, acc2[5][0]); acc2[5][1] = fma2(ar, B0.y, acc2[5][1]);
        acc2[5][2] = fma2(ar, B1.x, acc2[5][2]); acc2[5][3] = fma2(ar, B1.y, acc2[5][3]);
        ar = pack2(Ahi.z);
        acc2[6][0] = fma2(ar, B0.x, acc2[6][0]); acc2[6][1] = fma2(ar, B0.y, acc2[6][1]);
        acc2[6][2] = fma2(ar, B1.x, acc2[6][2]); acc2[6][3] = fma2(ar, B1.y, acc2[6][3]);
        ar = pack2(Ahi.w);
        acc2[7][0] = fma2(ar, B0.x, acc2[7][0]); acc2[7][1] = fma2(ar, B0.y, acc2[7][1]);
        acc2[7][2] = fma2(ar, B1.x, acc2[7][2]); acc2[7][3] = fma2(ar, B1.y, acc2[7][3]);
    }

    // ---- sigmoid + normal write interleaved per row ----
    int gjw = j0 + jb;
    #pragma unroll
    for (int r = 0; r < 8; r++) {
        acc2[r][0] = sig2(acc2[r][0]);
        acc2[r][1] = sig2(acc2[r][1]);
        acc2[r][2] = sig2(acc2[r][2]);
        acc2[r][3] = sig2(acc2[r][3]);
        int gi = i0 + ib + r;
        if (gi < NN && gjw < NN) {
            float4 o0 = make_float4(lo2(acc2[r][0]), hi2(acc2[r][0]),
                                    lo2(acc2[r][1]), hi2(acc2[r][1]));
            float4 o1 = make_float4(lo2(acc2[r][2]), hi2(acc2[r][2]),
                                    lo2(acc2[r][3]), hi2(acc2[r][3]));
            float* p = out + (size_t)gi * NN + gjw;
            __stcs((float4*)p, o0);
            __stcs((float4*)(p + 4), o1);
        }
    }

    if (bj == bi) return;   // diagonal tile: no mirror (all threads uniform)

    // ---- mirror write: single-pass full 128x128 transpose ----
    __syncthreads();        // all threads done reading in-tiles
    {
        int key    = tx & 7;         // = ((jb+c)>>3)&7 for all c in 0..7
        int c4base = ty << 1;        // = ib>>2
        #pragma unroll
        for (int c = 0; c < 8; c++) {
            int row = jb + c;        // staged j-local row 0..127
            int q   = c >> 1;
            float4 v0, v1;
            if (c & 1) {
                v0 = make_float4(hi2(acc2[0][q]), hi2(acc2[1][q]),
                                 hi2(acc2[2][q]), hi2(acc2[3][q]));
                v1 = make_float4(hi2(acc2[4][q]), hi2(acc2[5][q]),
                                 hi2(acc2[6][q]), hi2(acc2[7][q]));
            } else {
                v0 = make_float4(lo2(acc2[0][q]), lo2(acc2[1][q]),
                                 lo2(acc2[2][q]), lo2(acc2[3][q]));
                v1 = make_float4(lo2(acc2[4][q]), lo2(acc2[5][q]),
                                 lo2(acc2[6][q]), lo2(acc2[7][q]));
            }
            *(float4*)(tsf + row * 128 + (((c4base)     ^ key) << 2)) = v0;
            *(float4*)(tsf + row * 128 + (((c4base + 1) ^ key) << 2)) = v1;
        }
    }
    __syncthreads();
    {
        int warp = t >> 5, lane = t & 31;
        #pragma unroll
        for (int s = 0; s < 16; s++) {
            int row = (warp << 4) | s;           // j-local 0..127
            int key = (row >> 3) & 7;
            float4 val = *(const float4*)(tsf + row * 128 + ((lane ^ key) << 2));
            int gj = j0 + row;
            int gi = i0 + (lane << 2);
            if (gj < NN && gi < NN)
                __stcs((float4*)(out + (size_t)gj * NN + gi), val);
        }
    }
}

// ---------------- launch --------------------------------------------------
extern "C" void kernel_launch(void* const* d_in, const int* in_sizes, int n_in,
                              void* d_out, int out_size) {
    const float* x  = (const float*)d_in[0];
    const float* W1 = (const float*)d_in[1];
    const float* W2 = (const float*)d_in[2];
    const int*   ei = (const int*)  d_in[3];
    const float* ew = (const float*)d_in[4];

    float* out  = (float*)d_out;
    float* zout = out + (size_t)NN * NN;   // output layout: [adj (1e8) | z]

    cudaFuncSetAttribute(k_dec, cudaFuncAttributeMaxDynamicSharedMemorySize,
                         DEC_SMEM);

    k_build_gemm1<<<NB_GEMM1 + NB_BUILD, 256>>>(ei, ew, x, W1);
    k_spmm1_gemm2<<<(NN * 32 + 255) / 256, 256>>>(W2);
    k_spmm2      <<<(NN * 16) / 256, 256>>>(zout);
    k_dec        <<<NTRI, 256, DEC_SMEM>>>(zout, out);
}